// round 6
// baseline (speedup 1.0000x reference)
#include <cuda_runtime.h>
#include <cuda_bf16.h>
#include <math.h>

#define Bc   4
#define Pc   1024
#define Dc   512
#define Hc   8
#define DKc  64
#define HALFW 32
#define CONCAT_P (2*Pc)

#define M_PROJ (Bc * Pc)        // 4096
#define M_OUT  (Bc * CONCAT_P)  // 8192

// fp32 intermediates
__device__ float g_QKV[3 * M_PROJ * Dc];

// bf16 hi/lo split operands
__device__ __nv_bfloat16 g_Ahi[3 * M_PROJ * Dc];
__device__ __nv_bfloat16 g_Alo[3 * M_PROJ * Dc];
__device__ __nv_bfloat16 g_Bhi[4 * Dc * Dc];
__device__ __nv_bfloat16 g_Blo[4 * Dc * Dc];
__device__ __nv_bfloat16 g_Chi[M_OUT * Dc];
__device__ __nv_bfloat16 g_Clo[M_OUT * Dc];

// compact normalized attention windows: [which][b][h][i][128]
#define NROWS (2 * Bc * Hc * Pc)   // 65536
__device__ float g_Pwin[NROWS * 128];

// ---------------------------------------------------------------------------
__device__ __forceinline__ void split_bf16(float v, __nv_bfloat16& hi, __nv_bfloat16& lo)
{
    hi = __float2bfloat16(v);
    lo = __float2bfloat16(v - __bfloat162float(hi));
}

__global__ void split_a_kernel(const float* __restrict__ s0, const float* __restrict__ s1,
                               const float* __restrict__ s2,
                               __nv_bfloat16* __restrict__ hi, __nv_bfloat16* __restrict__ lo)
{
    int z = blockIdx.z;
    const float* src = (z == 0) ? s0 : (z == 1) ? s1 : s2;
    long long base = (long long)z * M_PROJ * Dc;
    long long n4 = (long long)M_PROJ * Dc / 4;
    long long idx = (long long)blockIdx.x * blockDim.x + threadIdx.x;
    long long stride = (long long)gridDim.x * blockDim.x;
    for (long long i = idx; i < n4; i += stride) {
        float4 v = ((const float4*)src)[i];
        __nv_bfloat16 h[4], l[4];
        split_bf16(v.x, h[0], l[0]);
        split_bf16(v.y, h[1], l[1]);
        split_bf16(v.z, h[2], l[2]);
        split_bf16(v.w, h[3], l[3]);
        long long o = base + i * 4;
        *(__nv_bfloat162*)&hi[o]     = __nv_bfloat162(h[0], h[1]);
        *(__nv_bfloat162*)&hi[o + 2] = __nv_bfloat162(h[2], h[3]);
        *(__nv_bfloat162*)&lo[o]     = __nv_bfloat162(l[0], l[1]);
        *(__nv_bfloat162*)&lo[o + 2] = __nv_bfloat162(l[2], l[3]);
    }
}

__global__ void split_b_kernel(const float* __restrict__ w0, const float* __restrict__ w1,
                               const float* __restrict__ w2, const float* __restrict__ w3,
                               __nv_bfloat16* __restrict__ hi, __nv_bfloat16* __restrict__ lo)
{
    __shared__ float t[32][33];
    int z = blockIdx.z;
    const float* W = (z == 0) ? w0 : (z == 1) ? w1 : (z == 2) ? w2 : w3;
    long long base = (long long)z * Dc * Dc;
    int n0 = blockIdx.x * 32;
    int k0 = blockIdx.y * 32;
    int tx = threadIdx.x, ty = threadIdx.y;
#pragma unroll
    for (int i = 0; i < 4; i++)
        t[ty + i * 8][tx] = W[(long long)(k0 + ty + i * 8) * Dc + n0 + tx];
    __syncthreads();
#pragma unroll
    for (int i = 0; i < 4; i++) {
        float v = t[tx][ty + i * 8];
        long long o = base + (long long)(n0 + ty + i * 8) * Dc + k0 + tx;
        __nv_bfloat16 h, l;
        split_bf16(v, h, l);
        hi[o] = h;
        lo[o] = l;
    }
}

// ---------------------------------------------------------------------------
// bf16-split GEMM (unchanged)
// ---------------------------------------------------------------------------
#define GS_STRIDE 40
#define GS_TILE   (128 * GS_STRIDE)
#define GS_STAGE  (4 * GS_TILE)
#define GEMM_SMEM_BYTES (2 * GS_STAGE * 2)   // 81920

__device__ __forceinline__ void cpasync16(void* dst_sh, const void* src)
{
    unsigned sh = (unsigned)__cvta_generic_to_shared(dst_sh);
    asm volatile("cp.async.cg.shared.global [%0], [%1], 16;\n" :: "r"(sh), "l"(src));
}

__device__ __forceinline__ void mma_bf16(float* d, const unsigned* a, const unsigned* b)
{
    asm volatile(
        "mma.sync.aligned.m16n8k16.row.col.f32.bf16.bf16.f32 "
        "{%0,%1,%2,%3}, {%4,%5,%6,%7}, {%8,%9}, {%0,%1,%2,%3};"
        : "+f"(d[0]), "+f"(d[1]), "+f"(d[2]), "+f"(d[3])
        : "r"(a[0]), "r"(a[1]), "r"(a[2]), "r"(a[3]), "r"(b[0]), "r"(b[1]));
}

__global__ __launch_bounds__(256)
void gemm_split_kernel(const __nv_bfloat16* __restrict__ Ah, const __nv_bfloat16* __restrict__ Al,
                       long long aStrideZ,
                       const __nv_bfloat16* __restrict__ Bh, const __nv_bfloat16* __restrict__ Bl,
                       long long bStrideZ,
                       float* __restrict__ C, long long cStrideZ,
                       const float* b0, const float* b1, const float* b2,
                       int M)
{
    extern __shared__ __nv_bfloat16 smem[];
    int z = blockIdx.z;
    Ah += (long long)z * aStrideZ;
    Al += (long long)z * aStrideZ;
    Bh += (long long)z * bStrideZ;
    Bl += (long long)z * bStrideZ;
    C  += (long long)z * cStrideZ;
    const float* bias = (z == 0) ? b0 : (z == 1) ? b1 : b2;

    int tid  = threadIdx.x;
    int lane = tid & 31;
    int warp = tid >> 5;
    int wm = (warp & 1) * 64;
    int wn = (warp >> 1) * 32;
    int row0 = blockIdx.y * 128;
    int col0 = blockIdx.x * 128;

    int cp_arr[8], cp_row[8], cp_c[8];
#pragma unroll
    for (int i = 0; i < 8; i++) {
        cp_arr[i] = i >> 1;
        int idx2 = ((i & 1) << 8) + tid;
        cp_row[i] = idx2 >> 2;
        cp_c[i] = (idx2 & 3) * 8;
    }

    float acc[4][4][4];
#pragma unroll
    for (int im = 0; im < 4; im++)
#pragma unroll
        for (int in_ = 0; in_ < 4; in_++)
#pragma unroll
            for (int r = 0; r < 4; r++) acc[im][in_][r] = 0.f;

    const int nIt = Dc / 32;

    auto load_stage = [&](int it, int s) {
        __nv_bfloat16* st = smem + s * GS_STAGE;
        int k0 = it * 32;
#pragma unroll
        for (int i = 0; i < 8; i++) {
            const __nv_bfloat16* src;
            int row = cp_row[i];
            int c = cp_c[i];
            if (cp_arr[i] == 0)      src = Ah + (long long)(row0 + row) * Dc + k0 + c;
            else if (cp_arr[i] == 1) src = Al + (long long)(row0 + row) * Dc + k0 + c;
            else if (cp_arr[i] == 2) src = Bh + (long long)(col0 + row) * Dc + k0 + c;
            else                     src = Bl + (long long)(col0 + row) * Dc + k0 + c;
            cpasync16(st + cp_arr[i] * GS_TILE + row * GS_STRIDE + c, src);
        }
        asm volatile("cp.async.commit_group;\n" ::);
    };

    load_stage(0, 0);

    for (int it = 0; it < nIt; it++) {
        int buf = it & 1;
        if (it + 1 < nIt) {
            load_stage(it + 1, buf ^ 1);
            asm volatile("cp.async.wait_group 1;\n" ::);
        } else {
            asm volatile("cp.async.wait_group 0;\n" ::);
        }
        __syncthreads();

        const __nv_bfloat16* sAh = smem + buf * GS_STAGE;
        const __nv_bfloat16* sAl = sAh + GS_TILE;
        const __nv_bfloat16* sBh = sAl + GS_TILE;
        const __nv_bfloat16* sBl = sBh + GS_TILE;

#pragma unroll
        for (int kk = 0; kk < 32; kk += 16) {
            int acol = kk + 2 * (lane & 3);
            unsigned a_h[4][4], a_l[4][4];
#pragma unroll
            for (int im = 0; im < 4; im++) {
                int rbase = wm + im * 16 + (lane >> 2);
#pragma unroll
                for (int r = 0; r < 4; r++) {
                    int row = rbase + (r & 1) * 8;
                    int col = acol + (r >> 1) * 8;
                    a_h[im][r] = *(const unsigned*)&sAh[row * GS_STRIDE + col];
                    a_l[im][r] = *(const unsigned*)&sAl[row * GS_STRIDE + col];
                }
            }
            unsigned b_h[4][2], b_l[4][2];
#pragma unroll
            for (int in_ = 0; in_ < 4; in_++) {
                int nrow = wn + in_ * 8 + (lane >> 2);
#pragma unroll
                for (int r = 0; r < 2; r++) {
                    int col = acol + r * 8;
                    b_h[in_][r] = *(const unsigned*)&sBh[nrow * GS_STRIDE + col];
                    b_l[in_][r] = *(const unsigned*)&sBl[nrow * GS_STRIDE + col];
                }
            }
#pragma unroll
            for (int im = 0; im < 4; im++)
#pragma unroll
                for (int in_ = 0; in_ < 4; in_++) {
                    mma_bf16(acc[im][in_], a_h[im], b_h[in_]);
                    mma_bf16(acc[im][in_], a_h[im], b_l[in_]);
                    mma_bf16(acc[im][in_], a_l[im], b_h[in_]);
                }
        }
        __syncthreads();
    }

#pragma unroll
    for (int im = 0; im < 4; im++) {
#pragma unroll
        for (int in_ = 0; in_ < 4; in_++) {
            int row = row0 + wm + im * 16 + (lane >> 2);
            int col = col0 + wn + in_ * 8 + 2 * (lane & 3);
            float2 bv = *(const float2*)&bias[col];
            float2 o0 = make_float2(acc[im][in_][0] + bv.x, acc[im][in_][1] + bv.y);
            float2 o1 = make_float2(acc[im][in_][2] + bv.x, acc[im][in_][3] + bv.y);
            *(float2*)&C[(long long)row * Dc + col]       = o0;
            *(float2*)&C[(long long)(row + 8) * Dc + col] = o1;
        }
    }
}

// ---------------------------------------------------------------------------
// Banded attention. grid = (Pc/64, Hc, Bc*2): z = b*2 + which.
// Writes concat (bf16 hi/lo) + compact normalized window Pwin (128 cols/row).
// ---------------------------------------------------------------------------
#define SM_QS 0
#define SM_KV 4352
#define SM_SS 13056
#define SM_INV 21504
#define ATTN_SMEM_BYTES (21568 * 4)

__global__ __launch_bounds__(256)
void attn_tile_kernel(const float* __restrict__ QKV,
                      __nv_bfloat16* __restrict__ Chi, __nv_bfloat16* __restrict__ Clo,
                      float* __restrict__ Pwin, int writeWin)
{
    extern __shared__ float sm[];
    float* Qs = sm + SM_QS;
    float* KV = sm + SM_KV;
    float* Ss = sm + SM_SS;
    float* sinv = sm + SM_INV;

    int tid = threadIdx.x;
    int q0 = blockIdx.x * 64;
    int h  = blockIdx.y;
    int zz = blockIdx.z;
    int b  = zz >> 1;
    int which = zz & 1;
    int k0 = q0 - HALFW;
    const float scale = 0.125f;

    const long long planeStride = (long long)M_PROJ * Dc;
    const float* Qp;
    const float* Kp;
    const float* Vp;
    int rowOffset;
    if (which == 0) {
        Qp = QKV;               Kp = QKV + planeStride; Vp = QKV + 2 * planeStride;
        rowOffset = 0;
    } else {
        Qp = QKV + planeStride; Kp = QKV;               Vp = QKV;
        rowOffset = Pc;
    }

    long long headBase = (long long)b * Pc * Dc + (long long)h * DKc;

    {
        int r = tid >> 2;
        int c = (tid & 3) * 16;
#pragma unroll
        for (int cc = 0; cc < 16; cc += 4) {
            float4 v = *(const float4*)&Qp[headBase + (long long)(q0 + r) * Dc + c + cc];
            Qs[(c + cc + 0) * 68 + r] = v.x;
            Qs[(c + cc + 1) * 68 + r] = v.y;
            Qs[(c + cc + 2) * 68 + r] = v.z;
            Qs[(c + cc + 3) * 68 + r] = v.w;
        }
    }
    for (int t = tid; t < 128 * 16; t += 256) {
        int r = t >> 4;
        int c = (t & 15) * 4;
        int j = k0 + r;
        float4 kv = make_float4(0.f, 0.f, 0.f, 0.f);
        if (j >= 0 && j < Pc)
            kv = *(const float4*)&Kp[headBase + (long long)j * Dc + c];
        KV[(c + 0) * 132 + r] = kv.x;
        KV[(c + 1) * 132 + r] = kv.y;
        KV[(c + 2) * 132 + r] = kv.z;
        KV[(c + 3) * 132 + r] = kv.w;
    }
    __syncthreads();

    // S = Q*K^T
    {
        int tx = tid & 15;
        int ty = tid >> 4;
        float acc[4][8];
#pragma unroll
        for (int i = 0; i < 4; i++)
#pragma unroll
            for (int j = 0; j < 8; j++) acc[i][j] = 0.f;

#pragma unroll 4
        for (int dd = 0; dd < 64; dd++) {
            float4 a  = *(const float4*)&Qs[dd * 68 + ty * 4];
            float4 b0 = *(const float4*)&KV[dd * 132 + tx * 8];
            float4 b1 = *(const float4*)&KV[dd * 132 + tx * 8 + 4];
            float ar[4] = {a.x, a.y, a.z, a.w};
            float br[8] = {b0.x, b0.y, b0.z, b0.w, b1.x, b1.y, b1.z, b1.w};
#pragma unroll
            for (int i = 0; i < 4; i++)
#pragma unroll
                for (int j = 0; j < 8; j++)
                    acc[i][j] = fmaf(ar[i], br[j], acc[i][j]);
        }
#pragma unroll
        for (int i = 0; i < 4; i++) {
            int row = ty * 4 + i;
            *(float4*)&Ss[row * 132 + tx * 8] =
                make_float4(acc[i][0], acc[i][1], acc[i][2], acc[i][3]);
            *(float4*)&Ss[row * 132 + tx * 8 + 4] =
                make_float4(acc[i][4], acc[i][5], acc[i][6], acc[i][7]);
        }
    }
    __syncthreads();

    // V over dead K region
    for (int t = tid; t < 128 * 16; t += 256) {
        int r = t >> 4;
        int c = (t & 15) * 4;
        int j = k0 + r;
        float4 vv = make_float4(0.f, 0.f, 0.f, 0.f);
        if (j >= 0 && j < Pc)
            vv = *(const float4*)&Vp[headBase + (long long)j * Dc + c];
        *(float4*)&KV[r * 68 + c] = vv;
    }

    // softmax: 4 threads/row
    {
        int qi = tid >> 2;
        int p  = tid & 3;
        int i_glob = q0 + qi;
        int jlo = i_glob - HALFW; if (jlo < 0) jlo = 0;
        int jhi = i_glob + HALFW; if (jhi > Pc - 1) jhi = Pc - 1;
        int kjlo = jlo - k0;
        int kjhi = jhi - k0;
        float* srow = &Ss[qi * 132];
        float m = -1e30f;
#pragma unroll 8
        for (int t = 0; t < 32; t++) {
            int kj = p + 4 * t;
            if (kj >= kjlo && kj <= kjhi) m = fmaxf(m, srow[kj]);
        }
        m = fmaxf(m, __shfl_xor_sync(0xffffffffu, m, 1));
        m = fmaxf(m, __shfl_xor_sync(0xffffffffu, m, 2));
        float sum = 0.f;
#pragma unroll 8
        for (int t = 0; t < 32; t++) {
            int kj = p + 4 * t;
            float pv = 0.f;
            if (kj >= kjlo && kj <= kjhi) {
                pv = __expf(scale * (srow[kj] - m));
                sum += pv;
            }
            srow[kj] = pv;
        }
        sum += __shfl_xor_sync(0xffffffffu, sum, 1);
        sum += __shfl_xor_sync(0xffffffffu, sum, 2);
        if (p == 0) sinv[qi] = 1.0f / sum;
    }
    __syncthreads();

    // O = P*V -> bf16 hi/lo concat
    {
        int txd = tid & 15;
        int tyq = tid >> 4;
        float acc[4][4];
#pragma unroll
        for (int i = 0; i < 4; i++)
#pragma unroll
            for (int j = 0; j < 4; j++) acc[i][j] = 0.f;

#pragma unroll 4
        for (int kj = 0; kj < 128; kj++) {
            float4 bv = *(const float4*)&KV[kj * 68 + txd * 4];
            float br[4] = {bv.x, bv.y, bv.z, bv.w};
#pragma unroll
            for (int i = 0; i < 4; i++) {
                float a = Ss[(tyq * 4 + i) * 132 + kj];
#pragma unroll
                for (int j = 0; j < 4; j++)
                    acc[i][j] = fmaf(a, br[j], acc[i][j]);
            }
        }
#pragma unroll
        for (int i = 0; i < 4; i++) {
            int qq = tyq * 4 + i;
            float inv = sinv[qq];
            long long dst = ((long long)b * CONCAT_P + rowOffset + q0 + qq) * Dc
                            + h * DKc + txd * 4;
            float o[4] = {acc[i][0] * inv, acc[i][1] * inv, acc[i][2] * inv, acc[i][3] * inv};
            __nv_bfloat16 hh[4], ll[4];
#pragma unroll
            for (int j = 0; j < 4; j++) split_bf16(o[j], hh[j], ll[j]);
            *(__nv_bfloat162*)&Chi[dst]     = __nv_bfloat162(hh[0], hh[1]);
            *(__nv_bfloat162*)&Chi[dst + 2] = __nv_bfloat162(hh[2], hh[3]);
            *(__nv_bfloat162*)&Clo[dst]     = __nv_bfloat162(ll[0], ll[1]);
            *(__nv_bfloat162*)&Clo[dst + 2] = __nv_bfloat162(ll[2], ll[3]);
        }
    }

    // Compact normalized window write: 64 rows x 128 cols, coalesced.
    if (writeWin) {
        long long prBase = ((long long)which * Bc * Hc + (long long)b * Hc + h) * Pc + q0;
#pragma unroll
        for (int t = tid; t < 64 * 32; t += 256) {
            int row = t >> 5;           // 0..63
            int c4  = (t & 31) * 4;     // 0..124
            float inv = sinv[row];
            const float* srow = &Ss[row * 132];
            float4 v = make_float4(srow[c4] * inv, srow[c4 + 1] * inv,
                                   srow[c4 + 2] * inv, srow[c4 + 3] * inv);
            *(float4*)&Pwin[(prBase + row) * 128 + c4] = v;
        }
    }
}

// ---------------------------------------------------------------------------
// Materialize dense A1|A2 from compact windows. Each block: 4 rows; each
// thread: one float4 column chunk per row (chunk is fully in/out of window
// since k0 % 4 == 0). Pure streaming stores.
// ---------------------------------------------------------------------------
__global__ __launch_bounds__(256)
void write_A_kernel(const float* __restrict__ Pwin, float* __restrict__ A1)
{
    int tid = threadIdx.x;
    int j0 = tid * 4;
    long long r0 = (long long)blockIdx.x * 4;
#pragma unroll
    for (int rr = 0; rr < 4; rr++) {
        long long r = r0 + rr;                 // global row in [0, 65536)
        int i = (int)(r & (Pc - 1));           // query index within (b,h)
        int k0 = ((i >> 6) << 6) - HALFW;      // window start (multiple of 4)
        float4 v = make_float4(0.f, 0.f, 0.f, 0.f);
        if (j0 >= k0 && j0 < k0 + 128)
            v = *(const float4*)&Pwin[r * 128 + (j0 - k0)];
        // dense layout: A1 then A2, both [b][h][i][j]; r already ordered so.
        __stcs((float4*)&A1[r * Pc + j0], v);
    }
}

// ---------------------------------------------------------------------------
extern "C" void kernel_launch(void* const* d_in, const int* in_sizes, int n_in,
                              void* d_out, int out_size)
{
    const float* queries = (const float*)d_in[0];
    const float* keys    = (const float*)d_in[1];
    const float* values  = (const float*)d_in[2];
    const float* Wq = (const float*)d_in[3];
    const float* bq = (const float*)d_in[4];
    const float* Wk = (const float*)d_in[5];
    const float* bk = (const float*)d_in[6];
    const float* Wv = (const float*)d_in[7];
    const float* bv = (const float*)d_in[8];
    const float* Wo = (const float*)d_in[9];
    const float* bo = (const float*)d_in[10];

    float* out = (float*)d_out;

    float *QKV, *Pwin;
    __nv_bfloat16 *Ahi, *Alo, *Bhi, *Blo, *Chi, *Clo;
    cudaGetSymbolAddress((void**)&QKV, g_QKV);
    cudaGetSymbolAddress((void**)&Pwin, g_Pwin);
    cudaGetSymbolAddress((void**)&Ahi, g_Ahi);
    cudaGetSymbolAddress((void**)&Alo, g_Alo);
    cudaGetSymbolAddress((void**)&Bhi, g_Bhi);
    cudaGetSymbolAddress((void**)&Blo, g_Blo);
    cudaGetSymbolAddress((void**)&Chi, g_Chi);
    cudaGetSymbolAddress((void**)&Clo, g_Clo);

    static int attr_set = 0;
    if (!attr_set) {
        cudaFuncSetAttribute(attn_tile_kernel,
                             cudaFuncAttributeMaxDynamicSharedMemorySize, ATTN_SMEM_BYTES);
        cudaFuncSetAttribute(gemm_split_kernel,
                             cudaFuncAttributeMaxDynamicSharedMemorySize, GEMM_SMEM_BYTES);
        attr_set = 1;
    }

    const long long mainN = (long long)M_OUT * Dc;
    const long long aN    = (long long)Bc * Hc * Pc * Pc;
    float* A1 = nullptr;
    bool hasA = ((long long)out_size >= mainN + 2 * aN);
    if (hasA) A1 = out + mainN;    // A2 = A1 + aN, contiguous, handled by writer

    split_a_kernel<<<dim3(256, 1, 3), 256>>>(queries, keys, values, Ahi, Alo);
    split_b_kernel<<<dim3(16, 16, 4), dim3(32, 8)>>>(Wq, Wk, Wv, Wo, Bhi, Blo);

    const long long aStride = (long long)M_PROJ * Dc;
    const long long bStride = (long long)Dc * Dc;
    gemm_split_kernel<<<dim3(Dc / 128, M_PROJ / 128, 3), 256, GEMM_SMEM_BYTES>>>(
        Ahi, Alo, aStride, Bhi, Blo, bStride, QKV, aStride, bq, bk, bv, M_PROJ);

    dim3 ga(Pc / 64, Hc, Bc * 2);
    attn_tile_kernel<<<ga, 256, ATTN_SMEM_BYTES>>>(QKV, Chi, Clo, Pwin, hasA ? 1 : 0);

    gemm_split_kernel<<<dim3(Dc / 128, M_OUT / 128, 1), 256, GEMM_SMEM_BYTES>>>(
        Chi, Clo, 0, Bhi + 3 * bStride, Blo + 3 * bStride, 0, out, 0, bo, bo, bo, M_OUT);

    if (hasA)
        write_A_kernel<<<NROWS / 4, 256>>>(Pwin, A1);
}

// round 7
// speedup vs baseline: 1.1526x; 1.1526x over previous
#include <cuda_runtime.h>
#include <cuda_bf16.h>
#include <math.h>

#define Bc   4
#define Pc   1024
#define Dc   512
#define Hc   8
#define DKc  64
#define HALFW 32
#define CONCAT_P (2*Pc)

#define M_PROJ (Bc * Pc)        // 4096
#define M_OUT  (Bc * CONCAT_P)  // 8192

// bf16 hi/lo split operands
__device__ __nv_bfloat16 g_Ahi[3 * M_PROJ * Dc];    // split inputs (GEMM A)
__device__ __nv_bfloat16 g_Alo[3 * M_PROJ * Dc];
__device__ __nv_bfloat16 g_Bhi[4 * Dc * Dc];        // weights [n][k]
__device__ __nv_bfloat16 g_Blo[4 * Dc * Dc];
__device__ __nv_bfloat16 g_QKVhi[3 * M_PROJ * Dc];  // projected Q|K|V hi
__device__ __nv_bfloat16 g_QKVlo[3 * M_PROJ * Dc];
__device__ __nv_bfloat16 g_Chi[M_OUT * Dc];         // concat (attn output)
__device__ __nv_bfloat16 g_Clo[M_OUT * Dc];

// ---------------------------------------------------------------------------
__device__ __forceinline__ void split_bf16(float v, __nv_bfloat16& hi, __nv_bfloat16& lo)
{
    hi = __float2bfloat16(v);
    lo = __float2bfloat16(v - __bfloat162float(hi));
}

__global__ void split_a_kernel(const float* __restrict__ s0, const float* __restrict__ s1,
                               const float* __restrict__ s2,
                               __nv_bfloat16* __restrict__ hi, __nv_bfloat16* __restrict__ lo)
{
    int z = blockIdx.z;
    const float* src = (z == 0) ? s0 : (z == 1) ? s1 : s2;
    long long base = (long long)z * M_PROJ * Dc;
    long long n4 = (long long)M_PROJ * Dc / 4;
    long long idx = (long long)blockIdx.x * blockDim.x + threadIdx.x;
    long long stride = (long long)gridDim.x * blockDim.x;
    for (long long i = idx; i < n4; i += stride) {
        float4 v = ((const float4*)src)[i];
        __nv_bfloat16 h[4], l[4];
        split_bf16(v.x, h[0], l[0]);
        split_bf16(v.y, h[1], l[1]);
        split_bf16(v.z, h[2], l[2]);
        split_bf16(v.w, h[3], l[3]);
        long long o = base + i * 4;
        *(__nv_bfloat162*)&hi[o]     = __nv_bfloat162(h[0], h[1]);
        *(__nv_bfloat162*)&hi[o + 2] = __nv_bfloat162(h[2], h[3]);
        *(__nv_bfloat162*)&lo[o]     = __nv_bfloat162(l[0], l[1]);
        *(__nv_bfloat162*)&lo[o + 2] = __nv_bfloat162(l[2], l[3]);
    }
}

__global__ void split_b_kernel(const float* __restrict__ w0, const float* __restrict__ w1,
                               const float* __restrict__ w2, const float* __restrict__ w3,
                               __nv_bfloat16* __restrict__ hi, __nv_bfloat16* __restrict__ lo)
{
    __shared__ float t[32][33];
    int z = blockIdx.z;
    const float* W = (z == 0) ? w0 : (z == 1) ? w1 : (z == 2) ? w2 : w3;
    long long base = (long long)z * Dc * Dc;
    int n0 = blockIdx.x * 32;
    int k0 = blockIdx.y * 32;
    int tx = threadIdx.x, ty = threadIdx.y;
#pragma unroll
    for (int i = 0; i < 4; i++)
        t[ty + i * 8][tx] = W[(long long)(k0 + ty + i * 8) * Dc + n0 + tx];
    __syncthreads();
#pragma unroll
    for (int i = 0; i < 4; i++) {
        float v = t[tx][ty + i * 8];
        long long o = base + (long long)(n0 + ty + i * 8) * Dc + k0 + tx;
        __nv_bfloat16 h, l;
        split_bf16(v, h, l);
        hi[o] = h;
        lo[o] = l;
    }
}

// ---------------------------------------------------------------------------
// bf16-split GEMM. Epilogue writes either fp32 C or bf16 hi/lo (Chi/Clo).
// ---------------------------------------------------------------------------
#define GS_STRIDE 40
#define GS_TILE   (128 * GS_STRIDE)
#define GS_STAGE  (4 * GS_TILE)
#define GEMM_SMEM_BYTES (2 * GS_STAGE * 2)   // 81920

__device__ __forceinline__ void cpasync16(void* dst_sh, const void* src)
{
    unsigned sh = (unsigned)__cvta_generic_to_shared(dst_sh);
    asm volatile("cp.async.cg.shared.global [%0], [%1], 16;\n" :: "r"(sh), "l"(src));
}

__device__ __forceinline__ void mma_bf16(float* d, const unsigned* a, const unsigned* b)
{
    asm volatile(
        "mma.sync.aligned.m16n8k16.row.col.f32.bf16.bf16.f32 "
        "{%0,%1,%2,%3}, {%4,%5,%6,%7}, {%8,%9}, {%0,%1,%2,%3};"
        : "+f"(d[0]), "+f"(d[1]), "+f"(d[2]), "+f"(d[3])
        : "r"(a[0]), "r"(a[1]), "r"(a[2]), "r"(a[3]), "r"(b[0]), "r"(b[1]));
}

__global__ __launch_bounds__(256)
void gemm_split_kernel(const __nv_bfloat16* __restrict__ Ah, const __nv_bfloat16* __restrict__ Al,
                       long long aStrideZ,
                       const __nv_bfloat16* __restrict__ Bh, const __nv_bfloat16* __restrict__ Bl,
                       long long bStrideZ,
                       float* C, __nv_bfloat16* Chi, __nv_bfloat16* Clo, long long cStrideZ,
                       const float* b0, const float* b1, const float* b2,
                       int M)
{
    extern __shared__ __nv_bfloat16 smem[];
    int z = blockIdx.z;
    Ah += (long long)z * aStrideZ;
    Al += (long long)z * aStrideZ;
    Bh += (long long)z * bStrideZ;
    Bl += (long long)z * bStrideZ;
    const float* bias = (z == 0) ? b0 : (z == 1) ? b1 : b2;

    int tid  = threadIdx.x;
    int lane = tid & 31;
    int warp = tid >> 5;
    int wm = (warp & 1) * 64;
    int wn = (warp >> 1) * 32;
    int row0 = blockIdx.y * 128;
    int col0 = blockIdx.x * 128;

    int cp_arr[8], cp_row[8], cp_c[8];
#pragma unroll
    for (int i = 0; i < 8; i++) {
        cp_arr[i] = i >> 1;
        int idx2 = ((i & 1) << 8) + tid;
        cp_row[i] = idx2 >> 2;
        cp_c[i] = (idx2 & 3) * 8;
    }

    float acc[4][4][4];
#pragma unroll
    for (int im = 0; im < 4; im++)
#pragma unroll
        for (int in_ = 0; in_ < 4; in_++)
#pragma unroll
            for (int r = 0; r < 4; r++) acc[im][in_][r] = 0.f;

    const int nIt = Dc / 32;

    auto load_stage = [&](int it, int s) {
        __nv_bfloat16* st = smem + s * GS_STAGE;
        int k0 = it * 32;
#pragma unroll
        for (int i = 0; i < 8; i++) {
            const __nv_bfloat16* src;
            int row = cp_row[i];
            int c = cp_c[i];
            if (cp_arr[i] == 0)      src = Ah + (long long)(row0 + row) * Dc + k0 + c;
            else if (cp_arr[i] == 1) src = Al + (long long)(row0 + row) * Dc + k0 + c;
            else if (cp_arr[i] == 2) src = Bh + (long long)(col0 + row) * Dc + k0 + c;
            else                     src = Bl + (long long)(col0 + row) * Dc + k0 + c;
            cpasync16(st + cp_arr[i] * GS_TILE + row * GS_STRIDE + c, src);
        }
        asm volatile("cp.async.commit_group;\n" ::);
    };

    load_stage(0, 0);

    for (int it = 0; it < nIt; it++) {
        int buf = it & 1;
        if (it + 1 < nIt) {
            load_stage(it + 1, buf ^ 1);
            asm volatile("cp.async.wait_group 1;\n" ::);
        } else {
            asm volatile("cp.async.wait_group 0;\n" ::);
        }
        __syncthreads();

        const __nv_bfloat16* sAh = smem + buf * GS_STAGE;
        const __nv_bfloat16* sAl = sAh + GS_TILE;
        const __nv_bfloat16* sBh = sAl + GS_TILE;
        const __nv_bfloat16* sBl = sBh + GS_TILE;

#pragma unroll
        for (int kk = 0; kk < 32; kk += 16) {
            int acol = kk + 2 * (lane & 3);
            unsigned a_h[4][4], a_l[4][4];
#pragma unroll
            for (int im = 0; im < 4; im++) {
                int rbase = wm + im * 16 + (lane >> 2);
#pragma unroll
                for (int r = 0; r < 4; r++) {
                    int row = rbase + (r & 1) * 8;
                    int col = acol + (r >> 1) * 8;
                    a_h[im][r] = *(const unsigned*)&sAh[row * GS_STRIDE + col];
                    a_l[im][r] = *(const unsigned*)&sAl[row * GS_STRIDE + col];
                }
            }
            unsigned b_h[4][2], b_l[4][2];
#pragma unroll
            for (int in_ = 0; in_ < 4; in_++) {
                int nrow = wn + in_ * 8 + (lane >> 2);
#pragma unroll
                for (int r = 0; r < 2; r++) {
                    int col = acol + r * 8;
                    b_h[in_][r] = *(const unsigned*)&sBh[nrow * GS_STRIDE + col];
                    b_l[in_][r] = *(const unsigned*)&sBl[nrow * GS_STRIDE + col];
                }
            }
#pragma unroll
            for (int im = 0; im < 4; im++)
#pragma unroll
                for (int in_ = 0; in_ < 4; in_++) {
                    mma_bf16(acc[im][in_], a_h[im], b_h[in_]);
                    mma_bf16(acc[im][in_], a_h[im], b_l[in_]);
                    mma_bf16(acc[im][in_], a_l[im], b_h[in_]);
                }
        }
        __syncthreads();
    }

#pragma unroll
    for (int im = 0; im < 4; im++) {
#pragma unroll
        for (int in_ = 0; in_ < 4; in_++) {
            int row = row0 + wm + im * 16 + (lane >> 2);
            int col = col0 + wn + in_ * 8 + 2 * (lane & 3);
            float2 bv = *(const float2*)&bias[col];
            float o0 = acc[im][in_][0] + bv.x, o1 = acc[im][in_][1] + bv.y;
            float o2 = acc[im][in_][2] + bv.x, o3 = acc[im][in_][3] + bv.y;
            if (C) {
                long long cb = (long long)z * cStrideZ;
                *(float2*)&C[cb + (long long)row * Dc + col]       = make_float2(o0, o1);
                *(float2*)&C[cb + (long long)(row + 8) * Dc + col] = make_float2(o2, o3);
            } else {
                long long cb = (long long)z * cStrideZ;
                __nv_bfloat16 h0, l0, h1, l1, h2, l2, h3, l3;
                split_bf16(o0, h0, l0); split_bf16(o1, h1, l1);
                split_bf16(o2, h2, l2); split_bf16(o3, h3, l3);
                *(__nv_bfloat162*)&Chi[cb + (long long)row * Dc + col]       = __nv_bfloat162(h0, h1);
                *(__nv_bfloat162*)&Clo[cb + (long long)row * Dc + col]       = __nv_bfloat162(l0, l1);
                *(__nv_bfloat162*)&Chi[cb + (long long)(row + 8) * Dc + col] = __nv_bfloat162(h2, h3);
                *(__nv_bfloat162*)&Clo[cb + (long long)(row + 8) * Dc + col] = __nv_bfloat162(l2, l3);
            }
        }
    }
}

// ---------------------------------------------------------------------------
// Tensor-core banded attention + fused dense A write.
// grid = (Pc/64, Hc, Bc*2); 256 threads (8 warps).
// ---------------------------------------------------------------------------
#define AQ_STRIDE 72     // bf16 stride, Q/K tiles
#define AS_STRIDE 132    // fp32 stride, S
#define AP_STRIDE 136    // bf16 stride, P / Vt
#define O_QHI 0
#define O_QLO 9216
#define O_KHI 18432
#define O_KLO 36864
#define O_SS  55296
#define O_PHI 89088
#define O_PLO 106496
#define O_VTHI 123904
#define O_VTLO 141312
#define O_SINV 158720
#define ATTN_SMEM_BYTES 158976

__global__ __launch_bounds__(256)
void attn_mma_kernel(const __nv_bfloat16* __restrict__ QKVhi,
                     const __nv_bfloat16* __restrict__ QKVlo,
                     __nv_bfloat16* __restrict__ Chi, __nv_bfloat16* __restrict__ Clo,
                     float* __restrict__ A1, float* __restrict__ A2)
{
    extern __shared__ char smraw[];
    __nv_bfloat16* sQh = (__nv_bfloat16*)(smraw + O_QHI);
    __nv_bfloat16* sQl = (__nv_bfloat16*)(smraw + O_QLO);
    __nv_bfloat16* sKh = (__nv_bfloat16*)(smraw + O_KHI);
    __nv_bfloat16* sKl = (__nv_bfloat16*)(smraw + O_KLO);
    float*         sS  = (float*)(smraw + O_SS);
    __nv_bfloat16* sPh = (__nv_bfloat16*)(smraw + O_PHI);
    __nv_bfloat16* sPl = (__nv_bfloat16*)(smraw + O_PLO);
    __nv_bfloat16* sVh = (__nv_bfloat16*)(smraw + O_VTHI);
    __nv_bfloat16* sVl = (__nv_bfloat16*)(smraw + O_VTLO);
    float*         sinv = (float*)(smraw + O_SINV);

    int tid  = threadIdx.x;
    int lane = tid & 31;
    int warp = tid >> 5;
    int q0 = blockIdx.x * 64;
    int h  = blockIdx.y;
    int zz = blockIdx.z;
    int b  = zz >> 1;
    int which = zz & 1;
    int k0 = q0 - HALFW;
    const float scale = 0.125f;

    const long long plane = (long long)M_PROJ * Dc;
    const __nv_bfloat16 *Qh, *Ql, *Kh, *Kl, *Vh, *Vl;
    int rowOffset;
    float* Aout;
    if (which == 0) {
        Qh = QKVhi;          Ql = QKVlo;
        Kh = QKVhi + plane;  Kl = QKVlo + plane;
        Vh = QKVhi + 2*plane; Vl = QKVlo + 2*plane;
        rowOffset = 0;  Aout = A1;
    } else {
        Qh = QKVhi + plane;  Ql = QKVlo + plane;
        Kh = QKVhi;          Kl = QKVlo;
        Vh = QKVhi;          Vl = QKVlo;
        rowOffset = Pc; Aout = A2;
    }
    long long headBase = (long long)b * Pc * Dc + (long long)h * DKc;

    const uint4 zero4 = make_uint4(0, 0, 0, 0);

    // Q tile (64 x 64 bf16) direct copy
    for (int t = tid; t < 512; t += 256) {
        int r = t >> 3, c = (t & 7) * 8;
        long long src = headBase + (long long)(q0 + r) * Dc + c;
        *(uint4*)&sQh[r * AQ_STRIDE + c] = *(const uint4*)&Qh[src];
        *(uint4*)&sQl[r * AQ_STRIDE + c] = *(const uint4*)&Ql[src];
    }
    // K tile (128 x 64 bf16), guard edges
    for (int t = tid; t < 1024; t += 256) {
        int r = t >> 3, c = (t & 7) * 8;
        int j = k0 + r;
        uint4 vh = zero4, vl = zero4;
        if (j >= 0 && j < Pc) {
            long long src = headBase + (long long)j * Dc + c;
            vh = *(const uint4*)&Kh[src];
            vl = *(const uint4*)&Kl[src];
        }
        *(uint4*)&sKh[r * AQ_STRIDE + c] = vh;
        *(uint4*)&sKl[r * AQ_STRIDE + c] = vl;
    }
    // V tile transposed: Vt[d][kj]
    for (int t = tid; t < 1024; t += 256) {
        int r = t & 127;             // kj
        int c = (t >> 7) * 8;        // d chunk
        int j = k0 + r;
        uint4 vh = zero4, vl = zero4;
        if (j >= 0 && j < Pc) {
            long long src = headBase + (long long)j * Dc + c;
            vh = *(const uint4*)&Vh[src];
            vl = *(const uint4*)&Vl[src];
        }
        const __nv_bfloat16* ph = (const __nv_bfloat16*)&vh;
        const __nv_bfloat16* pl = (const __nv_bfloat16*)&vl;
#pragma unroll
        for (int dd = 0; dd < 8; dd++) {
            sVh[(c + dd) * AP_STRIDE + r] = ph[dd];
            sVl[(c + dd) * AP_STRIDE + r] = pl[dd];
        }
    }
    __syncthreads();

    // ---- S = Q*K^T via bf16 split mma. Warp tile: m32 x n32, k64 ----
    {
        int m0 = (warp & 1) * 32;
        int n0 = (warp >> 1) * 32;
        float sacc[2][4][4];
#pragma unroll
        for (int mi = 0; mi < 2; mi++)
#pragma unroll
            for (int ni = 0; ni < 4; ni++)
#pragma unroll
                for (int r = 0; r < 4; r++) sacc[mi][ni][r] = 0.f;

#pragma unroll
        for (int ks = 0; ks < 4; ks++) {
            int kc = ks * 16 + 2 * (lane & 3);
            unsigned ah[2][4], al[2][4];
#pragma unroll
            for (int mi = 0; mi < 2; mi++) {
                int r = m0 + mi * 16 + (lane >> 2);
                ah[mi][0] = *(const unsigned*)&sQh[r * AQ_STRIDE + kc];
                ah[mi][1] = *(const unsigned*)&sQh[(r + 8) * AQ_STRIDE + kc];
                ah[mi][2] = *(const unsigned*)&sQh[r * AQ_STRIDE + kc + 8];
                ah[mi][3] = *(const unsigned*)&sQh[(r + 8) * AQ_STRIDE + kc + 8];
                al[mi][0] = *(const unsigned*)&sQl[r * AQ_STRIDE + kc];
                al[mi][1] = *(const unsigned*)&sQl[(r + 8) * AQ_STRIDE + kc];
                al[mi][2] = *(const unsigned*)&sQl[r * AQ_STRIDE + kc + 8];
                al[mi][3] = *(const unsigned*)&sQl[(r + 8) * AQ_STRIDE + kc + 8];
            }
            unsigned bh[4][2], bl[4][2];
#pragma unroll
            for (int ni = 0; ni < 4; ni++) {
                int n = n0 + ni * 8 + (lane >> 2);
                bh[ni][0] = *(const unsigned*)&sKh[n * AQ_STRIDE + kc];
                bh[ni][1] = *(const unsigned*)&sKh[n * AQ_STRIDE + kc + 8];
                bl[ni][0] = *(const unsigned*)&sKl[n * AQ_STRIDE + kc];
                bl[ni][1] = *(const unsigned*)&sKl[n * AQ_STRIDE + kc + 8];
            }
#pragma unroll
            for (int mi = 0; mi < 2; mi++)
#pragma unroll
                for (int ni = 0; ni < 4; ni++) {
                    mma_bf16(sacc[mi][ni], ah[mi], bh[ni]);
                    mma_bf16(sacc[mi][ni], ah[mi], bl[ni]);
                    mma_bf16(sacc[mi][ni], al[mi], bh[ni]);
                }
        }
        // write S to smem fp32
#pragma unroll
        for (int mi = 0; mi < 2; mi++)
#pragma unroll
            for (int ni = 0; ni < 4; ni++) {
                int r = m0 + mi * 16 + (lane >> 2);
                int cc = n0 + ni * 8 + 2 * (lane & 3);
                *(float2*)&sS[r * AS_STRIDE + cc] =
                    make_float2(sacc[mi][ni][0], sacc[mi][ni][1]);
                *(float2*)&sS[(r + 8) * AS_STRIDE + cc] =
                    make_float2(sacc[mi][ni][2], sacc[mi][ni][3]);
            }
    }
    __syncthreads();

    // ---- softmax (fp32), emit P bf16 hi/lo + keep unnormalized p in sS ----
    {
        int qi = tid >> 2;
        int p  = tid & 3;
        int i_glob = q0 + qi;
        int jlo = i_glob - HALFW; if (jlo < 0) jlo = 0;
        int jhi = i_glob + HALFW; if (jhi > Pc - 1) jhi = Pc - 1;
        int kjlo = jlo - k0;
        int kjhi = jhi - k0;
        float* srow = &sS[qi * AS_STRIDE];
        float m = -1e30f;
#pragma unroll 8
        for (int t = 0; t < 32; t++) {
            int kj = p + 4 * t;
            if (kj >= kjlo && kj <= kjhi) m = fmaxf(m, srow[kj]);
        }
        m = fmaxf(m, __shfl_xor_sync(0xffffffffu, m, 1));
        m = fmaxf(m, __shfl_xor_sync(0xffffffffu, m, 2));
        float sum = 0.f;
#pragma unroll 8
        for (int t = 0; t < 32; t++) {
            int kj = p + 4 * t;
            float pv = 0.f;
            if (kj >= kjlo && kj <= kjhi) {
                pv = __expf(scale * (srow[kj] - m));
                sum += pv;
            }
            srow[kj] = pv;
            __nv_bfloat16 hh, ll;
            split_bf16(pv, hh, ll);
            sPh[qi * AP_STRIDE + kj] = hh;
            sPl[qi * AP_STRIDE + kj] = ll;
        }
        sum += __shfl_xor_sync(0xffffffffu, sum, 1);
        sum += __shfl_xor_sync(0xffffffffu, sum, 2);
        if (p == 0) sinv[qi] = 1.0f / sum;
    }
    __syncthreads();

    // ---- fused dense A write: coalesced rows, streaming stores ----
    if (Aout) {
        int j0 = tid * 4;
        long long abase = ((long long)b * Hc + h) * Pc * (long long)Pc;
#pragma unroll 2
        for (int r = 0; r < 64; r++) {
            int i_glob = q0 + r;
            int jlo = i_glob - HALFW; if (jlo < 0) jlo = 0;
            int jhi = i_glob + HALFW; if (jhi > Pc - 1) jhi = Pc - 1;
            float inv = sinv[r];
            const float* srow = &sS[r * AS_STRIDE];
            float4 v = make_float4(0.f, 0.f, 0.f, 0.f);
            if (j0 + 3 >= jlo && j0 <= jhi) {
                int j;
                j = j0 + 0; if (j >= jlo && j <= jhi) v.x = srow[j - k0] * inv;
                j = j0 + 1; if (j >= jlo && j <= jhi) v.y = srow[j - k0] * inv;
                j = j0 + 2; if (j >= jlo && j <= jhi) v.z = srow[j - k0] * inv;
                j = j0 + 3; if (j >= jlo && j <= jhi) v.w = srow[j - k0] * inv;
            }
            __stcs((float4*)&Aout[abase + (long long)i_glob * Pc + j0], v);
        }
    }

    // ---- O = P*V via bf16 split mma. Warp tile: m32 x n16, k128 ----
    {
        int m0 = (warp & 1) * 32;
        int n0 = (warp >> 1) * 16;
        float oacc[2][2][4];
#pragma unroll
        for (int mi = 0; mi < 2; mi++)
#pragma unroll
            for (int ni = 0; ni < 2; ni++)
#pragma unroll
                for (int r = 0; r < 4; r++) oacc[mi][ni][r] = 0.f;

#pragma unroll
        for (int ks = 0; ks < 8; ks++) {
            int kc = ks * 16 + 2 * (lane & 3);
            unsigned ah[2][4], al[2][4];
#pragma unroll
            for (int mi = 0; mi < 2; mi++) {
                int r = m0 + mi * 16 + (lane >> 2);
                ah[mi][0] = *(const unsigned*)&sPh[r * AP_STRIDE + kc];
                ah[mi][1] = *(const unsigned*)&sPh[(r + 8) * AP_STRIDE + kc];
                ah[mi][2] = *(const unsigned*)&sPh[r * AP_STRIDE + kc + 8];
                ah[mi][3] = *(const unsigned*)&sPh[(r + 8) * AP_STRIDE + kc + 8];
                al[mi][0] = *(const unsigned*)&sPl[r * AP_STRIDE + kc];
                al[mi][1] = *(const unsigned*)&sPl[(r + 8) * AP_STRIDE + kc];
                al[mi][2] = *(const unsigned*)&sPl[r * AP_STRIDE + kc + 8];
                al[mi][3] = *(const unsigned*)&sPl[(r + 8) * AP_STRIDE + kc + 8];
            }
            unsigned bh[2][2], bl[2][2];
#pragma unroll
            for (int ni = 0; ni < 2; ni++) {
                int n = n0 + ni * 8 + (lane >> 2);
                bh[ni][0] = *(const unsigned*)&sVh[n * AP_STRIDE + kc];
                bh[ni][1] = *(const unsigned*)&sVh[n * AP_STRIDE + kc + 8];
                bl[ni][0] = *(const unsigned*)&sVl[n * AP_STRIDE + kc];
                bl[ni][1] = *(const unsigned*)&sVl[n * AP_STRIDE + kc + 8];
            }
#pragma unroll
            for (int mi = 0; mi < 2; mi++)
#pragma unroll
                for (int ni = 0; ni < 2; ni++) {
                    mma_bf16(oacc[mi][ni], ah[mi], bh[ni]);
                    mma_bf16(oacc[mi][ni], ah[mi], bl[ni]);
                    mma_bf16(oacc[mi][ni], al[mi], bh[ni]);
                }
        }

        // epilogue -> bf16 hi/lo concat
#pragma unroll
        for (int mi = 0; mi < 2; mi++)
#pragma unroll
            for (int ni = 0; ni < 2; ni++) {
                int qi0 = m0 + mi * 16 + (lane >> 2);
                int d   = n0 + ni * 8 + 2 * (lane & 3);
                float inv0 = sinv[qi0];
                float inv1 = sinv[qi0 + 8];
                float o0 = oacc[mi][ni][0] * inv0, o1 = oacc[mi][ni][1] * inv0;
                float o2 = oacc[mi][ni][2] * inv1, o3 = oacc[mi][ni][3] * inv1;
                long long dst0 = ((long long)b * CONCAT_P + rowOffset + q0 + qi0) * Dc
                                 + h * DKc + d;
                long long dst1 = dst0 + 8LL * Dc;
                __nv_bfloat16 h0, l0, h1, l1, h2, l2, h3, l3;
                split_bf16(o0, h0, l0); split_bf16(o1, h1, l1);
                split_bf16(o2, h2, l2); split_bf16(o3, h3, l3);
                *(__nv_bfloat162*)&Chi[dst0] = __nv_bfloat162(h0, h1);
                *(__nv_bfloat162*)&Clo[dst0] = __nv_bfloat162(l0, l1);
                *(__nv_bfloat162*)&Chi[dst1] = __nv_bfloat162(h2, h3);
                *(__nv_bfloat162*)&Clo[dst1] = __nv_bfloat162(l2, l3);
            }
    }
}

// ---------------------------------------------------------------------------
extern "C" void kernel_launch(void* const* d_in, const int* in_sizes, int n_in,
                              void* d_out, int out_size)
{
    const float* queries = (const float*)d_in[0];
    const float* keys    = (const float*)d_in[1];
    const float* values  = (const float*)d_in[2];
    const float* Wq = (const float*)d_in[3];
    const float* bq = (const float*)d_in[4];
    const float* Wk = (const float*)d_in[5];
    const float* bk = (const float*)d_in[6];
    const float* Wv = (const float*)d_in[7];
    const float* bv = (const float*)d_in[8];
    const float* Wo = (const float*)d_in[9];
    const float* bo = (const float*)d_in[10];

    float* out = (float*)d_out;

    __nv_bfloat16 *Ahi, *Alo, *Bhi, *Blo, *QKVhi, *QKVlo, *Chi, *Clo;
    cudaGetSymbolAddress((void**)&Ahi, g_Ahi);
    cudaGetSymbolAddress((void**)&Alo, g_Alo);
    cudaGetSymbolAddress((void**)&Bhi, g_Bhi);
    cudaGetSymbolAddress((void**)&Blo, g_Blo);
    cudaGetSymbolAddress((void**)&QKVhi, g_QKVhi);
    cudaGetSymbolAddress((void**)&QKVlo, g_QKVlo);
    cudaGetSymbolAddress((void**)&Chi, g_Chi);
    cudaGetSymbolAddress((void**)&Clo, g_Clo);

    static int attr_set = 0;
    if (!attr_set) {
        cudaFuncSetAttribute(attn_mma_kernel,
                             cudaFuncAttributeMaxDynamicSharedMemorySize, ATTN_SMEM_BYTES);
        cudaFuncSetAttribute(gemm_split_kernel,
                             cudaFuncAttributeMaxDynamicSharedMemorySize, GEMM_SMEM_BYTES);
        attr_set = 1;
    }

    const long long mainN = (long long)M_OUT * Dc;
    const long long aN    = (long long)Bc * Hc * Pc * Pc;
    float* A1 = nullptr;
    float* A2 = nullptr;
    if ((long long)out_size >= mainN + 2 * aN) {
        A1 = out + mainN;
        A2 = A1 + aN;
    }

    split_a_kernel<<<dim3(256, 1, 3), 256>>>(queries, keys, values, Ahi, Alo);
    split_b_kernel<<<dim3(16, 16, 4), dim3(32, 8)>>>(Wq, Wk, Wv, Wo, Bhi, Blo);

    const long long aStride = (long long)M_PROJ * Dc;
    const long long bStride = (long long)Dc * Dc;

    // projections: epilogue writes bf16 hi/lo Q|K|V
    gemm_split_kernel<<<dim3(Dc / 128, M_PROJ / 128, 3), 256, GEMM_SMEM_BYTES>>>(
        Ahi, Alo, aStride, Bhi, Blo, bStride,
        nullptr, QKVhi, QKVlo, aStride, bq, bk, bv, M_PROJ);

    dim3 ga(Pc / 64, Hc, Bc * 2);
    attn_mma_kernel<<<ga, 256, ATTN_SMEM_BYTES>>>(QKVhi, QKVlo, Chi, Clo, A1, A2);

    // output GEMM: fp32 out
    gemm_split_kernel<<<dim3(Dc / 128, M_OUT / 128, 1), 256, GEMM_SMEM_BYTES>>>(
        Chi, Clo, 0, Bhi + 3 * bStride, Blo + 3 * bStride, 0,
        out, nullptr, nullptr, 0, bo, bo, bo, M_OUT);
}